// round 16
// baseline (speedup 1.0000x reference)
#include <cuda_runtime.h>
#include <cstdint>
#include <math.h>

namespace {
constexpr int B_ = 2;
constexpr int C_ = 32;
constexpr int H_ = 128;
constexpr int W_ = 160;
constexpr int D_ = 32;
constexpr int N_ = 4;
constexpr int HW_ = H_ * W_;
constexpr int ROWB = W_ * 128;                 // bytes per image row (128B/pixel)
constexpr int PAD_F = 5248;                    // front guard pad (floats)
constexpr int BACK_F = 10496;                  // back guard pad (floats)
// per-warp smem: 4 views x 8 groups x stride 36  +  weight table 4 x 32 float4
constexpr int GSTRIDE = 36;
constexpr int VIEW_FLOATS = 8 * GSTRIDE;              // 288
constexpr int WARP_FLOATS = N_ * VIEW_FLOATS + N_ * 128;  // 1152 + 512 = 1664
}

#define FULLMASK 0xffffffffu

__device__ float g_src_buf[PAD_F + N_ * B_ * HW_ * C_ + BACK_F];  // padded src
__device__ float g_ref_t[B_ * HW_ * C_];       // [b][pix][c]
__device__ float g_dep_t[B_ * HW_ * D_];       // [b][pix][d]
__device__ float g_rt[B_ * N_ * 12];           // rot(9) + trans(3)

// ---------------------------------------------------------------------------
// Transpose all 12 planes; store side vectorized (one STG.128 per thread).
// ---------------------------------------------------------------------------
__global__ void transpose_all(const float* __restrict__ src,
                              const float* __restrict__ ref,
                              const float* __restrict__ dep,
                              float* __restrict__ osrc,
                              float* __restrict__ oref,
                              float* __restrict__ odep) {
    __shared__ float tile[32][33];
    const int z = blockIdx.z;
    const float* ip;
    float* op;
    if (z < 8) {
        ip = src + (size_t)z * 32 * HW_;
        op = osrc + (size_t)z * HW_ * 32;
    } else if (z < 10) {
        ip = ref + (size_t)(z - 8) * 32 * HW_;
        op = oref + (size_t)(z - 8) * HW_ * 32;
    } else {
        ip = dep + (size_t)(z - 10) * 32 * HW_;
        op = odep + (size_t)(z - 10) * HW_ * 32;
    }
    const int hw0 = blockIdx.x * 32;
    const int tx = threadIdx.x, ty = threadIdx.y;
#pragma unroll
    for (int k = 0; k < 32; k += 8)
        tile[ty + k][tx] = ip[(size_t)(ty + k) * HW_ + hw0 + tx];
    __syncthreads();
    // store: thread t -> row r = t&31 (hw), quad q = t>>5 (4 channels)
    const int t = ty * 32 + tx;
    const int r = t & 31;
    const int q = t >> 5;
    const float4 outv = make_float4(tile[q * 4 + 0][r], tile[q * 4 + 1][r],
                                    tile[q * 4 + 2][r], tile[q * 4 + 3][r]);
    *(float4*)(op + (size_t)(hw0 + r) * 32 + q * 4) = outv;
}

// ---------------------------------------------------------------------------
__device__ void build_new(const float* pm, int b, int vv, float Mo[4][4]) {
    const float* E = pm + (((b * (N_ + 1) + vv) * 2 + 0) * 16);
    const float* K = pm + (((b * (N_ + 1) + vv) * 2 + 1) * 16);
    for (int i = 0; i < 3; i++)
        for (int j = 0; j < 4; j++)
            Mo[i][j] = K[i * 4 + 0] * E[0 + j] + K[i * 4 + 1] * E[4 + j] + K[i * 4 + 2] * E[8 + j];
    for (int j = 0; j < 4; j++) Mo[3][j] = E[12 + j];
}

__global__ void setup_proj(const float* __restrict__ pm) {
    const int t = threadIdx.x;
    if (t >= B_ * N_) return;
    const int b = t / N_, v = t % N_;
    float R[4][4], S[4][4];
    build_new(pm, b, 0, R);
    build_new(pm, b, v + 1, S);
    float M[4][8];
    for (int i = 0; i < 4; i++)
        for (int j = 0; j < 4; j++) { M[i][j] = R[i][j]; M[i][4 + j] = (i == j) ? 1.f : 0.f; }
    for (int c = 0; c < 4; c++) {
        int piv = c;
        for (int r = c + 1; r < 4; r++)
            if (fabsf(M[r][c]) > fabsf(M[piv][c])) piv = r;
        if (piv != c)
            for (int j = 0; j < 8; j++) { float tmp = M[c][j]; M[c][j] = M[piv][j]; M[piv][j] = tmp; }
        const float ip = 1.f / M[c][c];
        for (int j = 0; j < 8; j++) M[c][j] *= ip;
        for (int r = 0; r < 4; r++)
            if (r != c) {
                const float f = M[r][c];
                for (int j = 0; j < 8; j++) M[r][j] -= f * M[c][j];
            }
    }
    float* o = g_rt + (b * N_ + v) * 12;
    for (int i = 0; i < 3; i++)
        for (int j = 0; j < 3; j++)
            o[i * 3 + j] = S[i][0] * M[0][4 + j] + S[i][1] * M[1][4 + j] +
                           S[i][2] * M[2][4 + j] + S[i][3] * M[3][4 + j];
    for (int i = 0; i < 3; i++)
        o[9 + i] = S[i][0] * M[0][7] + S[i][1] * M[1][7] + S[i][2] * M[2][7] + S[i][3] * M[3][7];
}

// ---------------------------------------------------------------------------
// Warp per pixel, 8 pixels per 256-thread block. FOUR depths per iteration.
// ALL 4 views' coordinates/weights precomputed before ONE syncwarp; the
// gather is a flat barrier-free 32-iteration stream (ptxas pipelines across
// view boundaries). Per iter: 1 SHFL + 1 LDS.128 + 4 LDG.128(imm) + 1 STS.
// Lane: cg=lane&7 (4-ch group), quarter=lane>>3 (depth in flight).
// ---------------------------------------------------------------------------
__global__ __launch_bounds__(256, 4) void stage_main(
    const float* __restrict__ regw, const float* __restrict__ regb,
    float* __restrict__ out_depth, float* __restrict__ out_attn) {
    __shared__ float sm[8 * WARP_FLOATS + 256];
    const int lane = threadIdx.x & 31;
    const int wi = threadIdx.x >> 5;
    const int x = blockIdx.x * 8 + wi;
    const int y = blockIdx.y;
    const int b = blockIdx.z;
    float* s4 = sm + wi * WARP_FLOATS;                 // 4 views x s[g*36 + d]
    float4* wtab = (float4*)(s4 + N_ * VIEW_FLOATS);   // [v][d] {w00,w10,w01,w11}
    float* stg = sm + 8 * WARP_FLOATS;                 // attn staging
    const int pix = y * W_ + x;
    const size_t pb32 = ((size_t)b * HW_ + pix) * 32;

    const int cg = lane & 7;
    const int quarter = lane >> 3;
    float4 refv = *(const float4*)(g_ref_t + pb32 + cg * 4);
    refv.x *= 0.25f; refv.y *= 0.25f; refv.z *= 0.25f; refv.w *= 0.25f;
    const float dl = g_dep_t[pb32 + lane];  // lane = depth index
    const float fx = (float)x, fy = (float)y;

    // ---- precompute ALL views: weights -> wtab, base offsets -> registers ----
    int off00A[N_];
#pragma unroll
    for (int v = 0; v < N_; v++) {
        const float* rt = g_rt + (b * N_ + v) * 12;
        const float rx = rt[0] * fx + rt[1] * fy + rt[2];
        const float ry = rt[3] * fx + rt[4] * fy + rt[5];
        const float rz = rt[6] * fx + rt[7] * fy + rt[8];
        float pz = rz * dl + rt[11];
        pz = (pz == 0.f) ? 1e-9f : pz;
        const float gx = __fdiv_rn(rx * dl + rt[9], pz);
        const float gy = __fdiv_rn(ry * dl + rt[10], pz);
        const float x0f = floorf(gx), y0f = floorf(gy);
        const float wx = gx - x0f, wy = gy - y0f;
        const float a0 = (1.f - wx) * (float)((x0f >= 0.f) & (x0f <= (float)(W_ - 1)));
        const float a1 = wx * (float)((x0f >= -1.f) & (x0f <= (float)(W_ - 2)));
        const float b0 = (1.f - wy) * (float)((y0f >= 0.f) & (y0f <= (float)(H_ - 1)));
        const float b1 = wy * (float)((y0f >= -1.f) & (y0f <= (float)(H_ - 2)));
        const int ix = (int)fminf(fmaxf(x0f, -1.f), (float)W_);
        const int iy = (int)fminf(fmaxf(y0f, -1.f), (float)H_);
        off00A[v] = (iy * W_ + ix) * 128;
        wtab[v * 32 + lane] = make_float4(a0 * b0, a1 * b0, a0 * b1, a1 * b1);
    }
    __syncwarp();

    // ---- flat barrier-free gather over all views (unrolled v keeps regs) ----
#pragma unroll
    for (int v = 0; v < N_; v++) {
        const char* svc = (const char*)(g_src_buf + PAD_F +
                                        ((size_t)(v * B_ + b)) * HW_ * 32 + cg * 4);
        float* ss = s4 + v * VIEW_FLOATS;
        const int myoff = off00A[v];
#pragma unroll 4
        for (int i = 0; i < D_ / 4; i++) {
            const int d = 4 * i + quarter;
            const int off = __shfl_sync(FULLMASK, myoff, d);
            const float4 Wv = wtab[v * 32 + d];  // LDS.128 broadcast
            const char* base = svc + off;
            const float4 v00 = __ldg((const float4*)(base));
            const float4 v10 = __ldg((const float4*)(base + 128));
            const float4 v01 = __ldg((const float4*)(base + ROWB));
            const float4 v11 = __ldg((const float4*)(base + ROWB + 128));
            const float d00 = v00.x * refv.x + v00.y * refv.y + v00.z * refv.z + v00.w * refv.w;
            const float d10 = v10.x * refv.x + v10.y * refv.y + v10.z * refv.z + v10.w * refv.w;
            const float d01 = v01.x * refv.x + v01.y * refv.y + v01.z * refv.z + v01.w * refv.w;
            const float d11 = v11.x * refv.x + v11.y * refv.y + v11.z * refv.z + v11.w * refv.w;
            ss[cg * GSTRIDE + d] = Wv.x * d00 + Wv.y * d10 + Wv.z * d01 + Wv.w * d11;
        }
    }
    __syncwarp();

    // ---- deferred epilogue: per-view softmax + register accumulation ----
    float f_g[8];
#pragma unroll
    for (int g = 0; g < 8; g++) f_g[g] = 0.f;
    float wsum = 1e-8f;

#pragma unroll
    for (int v = 0; v < N_; v++) {
        float sg[8];
#pragma unroll
        for (int g = 0; g < 8; g++) sg[g] = s4[v * VIEW_FLOATS + g * GSTRIDE + lane];
        float logit = ((sg[0] + sg[1]) + (sg[2] + sg[3])) +
                      ((sg[4] + sg[5]) + (sg[6] + sg[7]));
        logit *= 0.5f;
        float mx = logit;
#pragma unroll
        for (int o = 16; o > 0; o >>= 1) mx = fmaxf(mx, __shfl_xor_sync(FULLMASK, mx, o));
        const float e = __expf(logit - mx);
        float tot = e;
#pragma unroll
        for (int o = 16; o > 0; o >>= 1) tot += __shfl_xor_sync(FULLMASK, tot, o);
        const float w = __fdividef(e, tot) * 0.17677669529663687f;  // / sqrt(C)
        wsum += w;
#pragma unroll
        for (int g = 0; g < 8; g++) f_g[g] += w * sg[g];
    }

    // Final regression + softmax + argmax (lane = depth)
    float acc = 0.f;
#pragma unroll
    for (int g = 0; g < 8; g++) acc += f_g[g] * __ldg(regw + g);
    const float logit = __fdiv_rn(acc, wsum) + __ldg(regb);
    float mx = logit;
#pragma unroll
    for (int o = 16; o > 0; o >>= 1) mx = fmaxf(mx, __shfl_xor_sync(FULLMASK, mx, o));
    const float e = __expf(logit - mx);
    float tot = e;
#pragma unroll
    for (int o = 16; o > 0; o >>= 1) tot += __shfl_xor_sync(FULLMASK, tot, o);
    const float attn = __fdividef(e, tot);

    float bv = attn;
    int bi = lane;
#pragma unroll
    for (int o = 16; o > 0; o >>= 1) {
        const float ov = __shfl_xor_sync(FULLMASK, bv, o);
        const int oi = __shfl_xor_sync(FULLMASK, bi, o);
        if (ov > bv || (ov == bv && oi < bi)) { bv = ov; bi = oi; }
    }
    const float dsel = __shfl_sync(FULLMASK, dl, bi);
    if (lane == 0) out_depth[(b * H_ + y) * W_ + x] = dsel;

    stg[wi * 32 + lane] = attn;
    __syncthreads();
    const int t = threadIdx.x;
    const int dd = t >> 3, wj = t & 7;
    out_attn[(((size_t)b * D_ + dd) * H_ + y) * W_ + blockIdx.x * 8 + wj] =
        stg[wj * 32 + dd];
}

// ---------------------------------------------------------------------------
extern "C" void kernel_launch(void* const* d_in, const int* in_sizes, int n_in,
                              void* d_out, int out_size) {
    const float* ref = (const float*)d_in[0];
    const float* src = (const float*)d_in[1];
    const float* pm  = (const float*)d_in[2];
    const float* dep = (const float*)d_in[3];
    const float* rw  = (const float*)d_in[4];
    const float* rb  = (const float*)d_in[5];
    float* out_depth = (float*)d_out;
    float* out_attn  = out_depth + (size_t)B_ * HW_;

    float *g_buf_p, *g_ref_p, *g_dep_p;
    cudaGetSymbolAddress((void**)&g_buf_p, g_src_buf);
    cudaGetSymbolAddress((void**)&g_ref_p, g_ref_t);
    cudaGetSymbolAddress((void**)&g_dep_p, g_dep_t);
    float* g_src_p = g_buf_p + PAD_F;  // transposed src lives after front pad

    dim3 tb(32, 8);
    transpose_all<<<dim3(HW_ / 32, 1, 12), tb>>>(src, ref, dep, g_src_p, g_ref_p, g_dep_p);
    setup_proj<<<1, 32>>>(pm);
    stage_main<<<dim3(W_ / 8, H_, B_), 256>>>(rw, rb, out_depth, out_attn);
}

// round 17
// speedup vs baseline: 1.0752x; 1.0752x over previous
#include <cuda_runtime.h>
#include <cstdint>
#include <math.h>

namespace {
constexpr int B_ = 2;
constexpr int C_ = 32;
constexpr int H_ = 128;
constexpr int W_ = 160;
constexpr int D_ = 32;
constexpr int N_ = 4;
constexpr int HW_ = H_ * W_;
constexpr int ROWB = W_ * 128;                 // bytes per image row (128B/pixel)
constexpr int PAD_F = 5248;                    // front guard pad (floats)
constexpr int BACK_F = 10496;                  // back guard pad (floats)
// per-warp smem: 4 views x 8 groups x stride 36  +  weight table 32 x float4
constexpr int GSTRIDE = 36;
constexpr int VIEW_FLOATS = 8 * GSTRIDE;       // 288
constexpr int WARP_FLOATS = N_ * VIEW_FLOATS + 128;  // 1280 (42KB/block -> L1D ~60KB)
}

#define FULLMASK 0xffffffffu

__device__ float g_src_buf[PAD_F + N_ * B_ * HW_ * C_ + BACK_F];  // padded src
__device__ float g_ref_t[B_ * HW_ * C_];       // [b][pix][c]
__device__ float g_dep_t[B_ * HW_ * D_];       // [b][pix][d]
__device__ float g_rt[B_ * N_ * 12];           // rot(9) + trans(3)

// ---------------------------------------------------------------------------
// Transpose all 12 planes ([P][32][HW] -> [P][HW][32]); scalar, fully
// coalesced both sides (R15-proven: 13.4us).
// ---------------------------------------------------------------------------
__global__ void transpose_all(const float* __restrict__ src,
                              const float* __restrict__ ref,
                              const float* __restrict__ dep,
                              float* __restrict__ osrc,
                              float* __restrict__ oref,
                              float* __restrict__ odep) {
    __shared__ float tile[32][33];
    const int z = blockIdx.z;
    const float* ip;
    float* op;
    if (z < 8) {
        ip = src + (size_t)z * 32 * HW_;
        op = osrc + (size_t)z * HW_ * 32;
    } else if (z < 10) {
        ip = ref + (size_t)(z - 8) * 32 * HW_;
        op = oref + (size_t)(z - 8) * HW_ * 32;
    } else {
        ip = dep + (size_t)(z - 10) * 32 * HW_;
        op = odep + (size_t)(z - 10) * HW_ * 32;
    }
    const int hw0 = blockIdx.x * 32;
    const int tx = threadIdx.x, ty = threadIdx.y;
#pragma unroll
    for (int k = 0; k < 32; k += 8)
        tile[ty + k][tx] = ip[(size_t)(ty + k) * HW_ + hw0 + tx];
    __syncthreads();
#pragma unroll
    for (int k = 0; k < 32; k += 8)
        op[(size_t)(hw0 + ty + k) * 32 + tx] = tile[tx][ty + k];
}

// ---------------------------------------------------------------------------
__device__ void build_new(const float* pm, int b, int vv, float Mo[4][4]) {
    const float* E = pm + (((b * (N_ + 1) + vv) * 2 + 0) * 16);
    const float* K = pm + (((b * (N_ + 1) + vv) * 2 + 1) * 16);
    for (int i = 0; i < 3; i++)
        for (int j = 0; j < 4; j++)
            Mo[i][j] = K[i * 4 + 0] * E[0 + j] + K[i * 4 + 1] * E[4 + j] + K[i * 4 + 2] * E[8 + j];
    for (int j = 0; j < 4; j++) Mo[3][j] = E[12 + j];
}

__global__ void setup_proj(const float* __restrict__ pm) {
    const int t = threadIdx.x;
    if (t >= B_ * N_) return;
    const int b = t / N_, v = t % N_;
    float R[4][4], S[4][4];
    build_new(pm, b, 0, R);
    build_new(pm, b, v + 1, S);
    float M[4][8];
    for (int i = 0; i < 4; i++)
        for (int j = 0; j < 4; j++) { M[i][j] = R[i][j]; M[i][4 + j] = (i == j) ? 1.f : 0.f; }
    for (int c = 0; c < 4; c++) {
        int piv = c;
        for (int r = c + 1; r < 4; r++)
            if (fabsf(M[r][c]) > fabsf(M[piv][c])) piv = r;
        if (piv != c)
            for (int j = 0; j < 8; j++) { float tmp = M[c][j]; M[c][j] = M[piv][j]; M[piv][j] = tmp; }
        const float ip = 1.f / M[c][c];
        for (int j = 0; j < 8; j++) M[c][j] *= ip;
        for (int r = 0; r < 4; r++)
            if (r != c) {
                const float f = M[r][c];
                for (int j = 0; j < 8; j++) M[r][j] -= f * M[c][j];
            }
    }
    float* o = g_rt + (b * N_ + v) * 12;
    for (int i = 0; i < 3; i++)
        for (int j = 0; j < 3; j++)
            o[i * 3 + j] = S[i][0] * M[0][4 + j] + S[i][1] * M[1][4 + j] +
                           S[i][2] * M[2][4 + j] + S[i][3] * M[3][4 + j];
    for (int i = 0; i < 3; i++)
        o[9 + i] = S[i][0] * M[0][7] + S[i][1] * M[1][7] + S[i][2] * M[2][7] + S[i][3] * M[3][7];
}

// ---------------------------------------------------------------------------
// Warp per pixel, 8 pixels per 256-thread block. FOUR depths per iteration,
// per-view precompute (keeps smem at 42KB/block -> L1D ~60KB preserved).
// Per iter: 1 SHFL + 1 LDS.128 + 4 LDG.128(imm offsets) + 1 STS.
// Depth loop FULLY unrolled (whole view's 32-LDG stream visible to ptxas).
// Lane: cg=lane&7 (4-ch group), quarter=lane>>3 (depth in flight).
// ---------------------------------------------------------------------------
__global__ __launch_bounds__(256, 4) void stage_main(
    const float* __restrict__ regw, const float* __restrict__ regb,
    float* __restrict__ out_depth, float* __restrict__ out_attn) {
    __shared__ float sm[8 * WARP_FLOATS + 256];
    const int lane = threadIdx.x & 31;
    const int wi = threadIdx.x >> 5;
    const int x = blockIdx.x * 8 + wi;
    const int y = blockIdx.y;
    const int b = blockIdx.z;
    float* s4 = sm + wi * WARP_FLOATS;           // 4 views x s[g*36 + d]
    float4* wtab = (float4*)(s4 + N_ * VIEW_FLOATS);  // [d] {w00,w10,w01,w11}
    float* stg = sm + 8 * WARP_FLOATS;           // attn staging
    const int pix = y * W_ + x;
    const size_t pb32 = ((size_t)b * HW_ + pix) * 32;

    const int cg = lane & 7;
    const int quarter = lane >> 3;
    float4 refv = *(const float4*)(g_ref_t + pb32 + cg * 4);
    refv.x *= 0.25f; refv.y *= 0.25f; refv.z *= 0.25f; refv.w *= 0.25f;
    const float dl = g_dep_t[pb32 + lane];  // lane = depth index
    const float fx = (float)x, fy = (float)y;

#pragma unroll
    for (int v = 0; v < N_; v++) {
        const float* rt = g_rt + (b * N_ + v) * 12;
        const float rx = rt[0] * fx + rt[1] * fy + rt[2];
        const float ry = rt[3] * fx + rt[4] * fy + rt[5];
        const float rz = rt[6] * fx + rt[7] * fy + rt[8];
        const char* svc = (const char*)(g_src_buf + PAD_F +
                                        ((size_t)(v * B_ + b)) * HW_ * 32 + cg * 4);
        float* ss = s4 + v * VIEW_FLOATS;

        // ---- per-lane (lane = depth) coords, weights, base byte offset ----
        int off00;
        {
            float pz = rz * dl + rt[11];
            pz = (pz == 0.f) ? 1e-9f : pz;
            const float gx = __fdiv_rn(rx * dl + rt[9], pz);
            const float gy = __fdiv_rn(ry * dl + rt[10], pz);
            const float x0f = floorf(gx), y0f = floorf(gy);
            const float wx = gx - x0f, wy = gy - y0f;
            const float a0 = (1.f - wx) * (float)((x0f >= 0.f) & (x0f <= (float)(W_ - 1)));
            const float a1 = wx * (float)((x0f >= -1.f) & (x0f <= (float)(W_ - 2)));
            const float b0 = (1.f - wy) * (float)((y0f >= 0.f) & (y0f <= (float)(H_ - 1)));
            const float b1 = wy * (float)((y0f >= -1.f) & (y0f <= (float)(H_ - 2)));
            // valid taps keep exact addresses; invalid taps land in pad with w=0
            const int ix = (int)fminf(fmaxf(x0f, -1.f), (float)W_);
            const int iy = (int)fminf(fmaxf(y0f, -1.f), (float)H_);
            off00 = (iy * W_ + ix) * 128;
            wtab[lane] = make_float4(a0 * b0, a1 * b0, a0 * b1, a1 * b1);
        }
        __syncwarp();

        // ---- gather: 4 depths/iter, full view unrolled ----
#pragma unroll
        for (int i = 0; i < D_ / 4; i++) {
            const int d = 4 * i + quarter;
            const int off = __shfl_sync(FULLMASK, off00, d);
            const float4 Wv = wtab[d];  // LDS.128 broadcast (off load-addr path)
            const char* base = svc + off;
            const float4 v00 = __ldg((const float4*)(base));
            const float4 v10 = __ldg((const float4*)(base + 128));
            const float4 v01 = __ldg((const float4*)(base + ROWB));
            const float4 v11 = __ldg((const float4*)(base + ROWB + 128));
            const float d00 = v00.x * refv.x + v00.y * refv.y + v00.z * refv.z + v00.w * refv.w;
            const float d10 = v10.x * refv.x + v10.y * refv.y + v10.z * refv.z + v10.w * refv.w;
            const float d01 = v01.x * refv.x + v01.y * refv.y + v01.z * refv.z + v01.w * refv.w;
            const float d11 = v11.x * refv.x + v11.y * refv.y + v11.z * refv.z + v11.w * refv.w;
            ss[cg * GSTRIDE + d] = Wv.x * d00 + Wv.y * d10 + Wv.z * d01 + Wv.w * d11;
        }
        __syncwarp();  // wtab reads done before next view overwrites
    }

    // ---- deferred epilogue: per-view softmax + register accumulation ----
    float f_g[8];
#pragma unroll
    for (int g = 0; g < 8; g++) f_g[g] = 0.f;
    float wsum = 1e-8f;

#pragma unroll
    for (int v = 0; v < N_; v++) {
        float sg[8];
#pragma unroll
        for (int g = 0; g < 8; g++) sg[g] = s4[v * VIEW_FLOATS + g * GSTRIDE + lane];
        float logit = ((sg[0] + sg[1]) + (sg[2] + sg[3])) +
                      ((sg[4] + sg[5]) + (sg[6] + sg[7]));
        logit *= 0.5f;
        float mx = logit;
#pragma unroll
        for (int o = 16; o > 0; o >>= 1) mx = fmaxf(mx, __shfl_xor_sync(FULLMASK, mx, o));
        const float e = __expf(logit - mx);
        float tot = e;
#pragma unroll
        for (int o = 16; o > 0; o >>= 1) tot += __shfl_xor_sync(FULLMASK, tot, o);
        const float w = __fdividef(e, tot) * 0.17677669529663687f;  // / sqrt(C)
        wsum += w;
#pragma unroll
        for (int g = 0; g < 8; g++) f_g[g] += w * sg[g];
    }

    // Final regression + softmax + argmax (lane = depth)
    float acc = 0.f;
#pragma unroll
    for (int g = 0; g < 8; g++) acc += f_g[g] * __ldg(regw + g);
    const float logit = __fdiv_rn(acc, wsum) + __ldg(regb);
    float mx = logit;
#pragma unroll
    for (int o = 16; o > 0; o >>= 1) mx = fmaxf(mx, __shfl_xor_sync(FULLMASK, mx, o));
    const float e = __expf(logit - mx);
    float tot = e;
#pragma unroll
    for (int o = 16; o > 0; o >>= 1) tot += __shfl_xor_sync(FULLMASK, tot, o);
    const float attn = __fdividef(e, tot);

    float bv = attn;
    int bi = lane;
#pragma unroll
    for (int o = 16; o > 0; o >>= 1) {
        const float ov = __shfl_xor_sync(FULLMASK, bv, o);
        const int oi = __shfl_xor_sync(FULLMASK, bi, o);
        if (ov > bv || (ov == bv && oi < bi)) { bv = ov; bi = oi; }
    }
    const float dsel = __shfl_sync(FULLMASK, dl, bi);
    if (lane == 0) out_depth[(b * H_ + y) * W_ + x] = dsel;

    stg[wi * 32 + lane] = attn;
    __syncthreads();
    const int t = threadIdx.x;
    const int dd = t >> 3, wj = t & 7;
    out_attn[(((size_t)b * D_ + dd) * H_ + y) * W_ + blockIdx.x * 8 + wj] =
        stg[wj * 32 + dd];
}

// ---------------------------------------------------------------------------
extern "C" void kernel_launch(void* const* d_in, const int* in_sizes, int n_in,
                              void* d_out, int out_size) {
    const float* ref = (const float*)d_in[0];
    const float* src = (const float*)d_in[1];
    const float* pm  = (const float*)d_in[2];
    const float* dep = (const float*)d_in[3];
    const float* rw  = (const float*)d_in[4];
    const float* rb  = (const float*)d_in[5];
    float* out_depth = (float*)d_out;
    float* out_attn  = out_depth + (size_t)B_ * HW_;

    float *g_buf_p, *g_ref_p, *g_dep_p;
    cudaGetSymbolAddress((void**)&g_buf_p, g_src_buf);
    cudaGetSymbolAddress((void**)&g_ref_p, g_ref_t);
    cudaGetSymbolAddress((void**)&g_dep_p, g_dep_t);
    float* g_src_p = g_buf_p + PAD_F;  // transposed src lives after front pad

    dim3 tb(32, 8);
    transpose_all<<<dim3(HW_ / 32, 1, 12), tb>>>(src, ref, dep, g_src_p, g_ref_p, g_dep_p);
    setup_proj<<<1, 32>>>(pm);
    stage_main<<<dim3(W_ / 8, H_, B_), 256>>>(rw, rb, out_depth, out_attn);
}